// round 6
// baseline (speedup 1.0000x reference)
#include <cuda_runtime.h>
#include <cuda_bf16.h>
#include <math.h>

#define D_   1024
#define H_   16
#define V_   50257
#define L_   4
#define B_   2
#define S_   1024
#define DK_  64
#define DFF_ 4096
#define NTOK (B_ * S_)
#define NEGF (-3.402823466e38f)

// ---------------------------------------------------------------------------
// Device scratch
// ---------------------------------------------------------------------------
__device__ float g_x [NTOK * D_];
__device__ float g_xr[NTOK * D_];        // tf32-rounded shadow of x
__device__ float g_q [NTOK * D_];
__device__ float g_k [NTOK * D_];
__device__ float g_v [NTOK * D_];
__device__ float g_y [NTOK * D_];
__device__ float g_ln[NTOK * D_];
__device__ float g_h1[NTOK * DFF_];
__device__ float g_p [2 * NTOK * D_];    // split-K partials

__device__ __forceinline__ float gelu_exact(float v) {
    return 0.5f * v * (1.0f + erff(v * 0.70710678118654752440f));
}

__device__ __forceinline__ unsigned f2tf32(float x) {
    unsigned u;
    asm("cvt.rna.tf32.f32 %0, %1;" : "=r"(u) : "f"(x));
    return u;
}
__device__ __forceinline__ float f2tf32f(float x) { return __uint_as_float(f2tf32(x)); }

__device__ __forceinline__ void mma_tf32(float* c, const unsigned* a, const unsigned* b) {
    asm volatile(
        "mma.sync.aligned.m16n8k8.row.col.f32.tf32.tf32.f32 "
        "{%0,%1,%2,%3},{%4,%5,%6,%7},{%8,%9},{%0,%1,%2,%3};"
        : "+f"(c[0]), "+f"(c[1]), "+f"(c[2]), "+f"(c[3])
        : "r"(a[0]), "r"(a[1]), "r"(a[2]), "r"(a[3]), "r"(b[0]), "r"(b[1]));
}

__device__ __forceinline__ void cp16(float* s, const float* g, bool pred) {
    unsigned sa = (unsigned)__cvta_generic_to_shared(s);
    int sz = pred ? 16 : 0;
    asm volatile("cp.async.cg.shared.global [%0], [%1], 16, %2;\n"
                 :: "r"(sa), "l"(g), "r"(sz));
}
__device__ __forceinline__ void cp_commit() {
    asm volatile("cp.async.commit_group;\n" ::: "memory");
}

// ---------------------------------------------------------------------------
// Embedding: x and rounded shadow xr
// ---------------------------------------------------------------------------
__global__ void embed_kernel(const int* __restrict__ idx,
                             const float* __restrict__ te,
                             const float* __restrict__ pe,
                             float* __restrict__ x, float* __restrict__ xr) {
    int row = blockIdx.x;
    int s   = row % S_;
    int tok = idx[row];
    int c   = threadIdx.x * 4;
    float4 t = *(const float4*)(te + (size_t)tok * D_ + c);
    float4 p = *(const float4*)(pe + (size_t)s   * D_ + c);
    float4 o = make_float4(t.x + p.x, t.y + p.y, t.z + p.z, t.w + p.w);
    *(float4*)(x + (size_t)row * D_ + c) = o;
    float4 r;
    r.x = f2tf32f(o.x); r.y = f2tf32f(o.y); r.z = f2tf32f(o.z); r.w = f2tf32f(o.w);
    *(float4*)(xr + (size_t)row * D_ + c) = r;
}

// ---------------------------------------------------------------------------
// Fused flash attention (tf32 MMA, online softmax); epilogue rounds y to tf32
// ---------------------------------------------------------------------------
__global__ void __launch_bounds__(256, 2)
flash_attn(const float* __restrict__ q, const float* __restrict__ k,
           const float* __restrict__ v, float* __restrict__ y)
{
    constexpr int KSTR = 76, VSTR = 76;
    __shared__ float Ks[64 * KSTR];
    __shared__ float Vs[64 * VSTR];

    const int xmap[8] = {0, 7, 1, 6, 2, 5, 3, 4};
    const int m0  = xmap[blockIdx.x] * 128;
    const int bh  = blockIdx.y;
    const int b   = bh >> 4, h = bh & 15;
    const int tid = threadIdx.x;
    const int wid = tid >> 5, lane = tid & 31;
    const int g   = lane >> 2, tq = lane & 3;
    const int rowbase = wid * 16;
    const int r0 = m0 + rowbase + g;
    const int r8 = r0 + 8;
    const int RS = H_ * DK_;

    unsigned qf[8][4];
    {
        const float* q0 = q + (size_t)(b * S_ + r0) * RS + h * DK_;
        const float* q8 = q0 + 8 * RS;
        #pragma unroll
        for (int ks = 0; ks < 8; ks++) {
            qf[ks][0] = f2tf32(0.125f * q0[8 * ks + tq]);
            qf[ks][1] = f2tf32(0.125f * q8[8 * ks + tq]);
            qf[ks][2] = f2tf32(0.125f * q0[8 * ks + tq + 4]);
            qf[ks][3] = f2tf32(0.125f * q8[8 * ks + tq + 4]);
        }
    }

    float o[8][4];
    #pragma unroll
    for (int j = 0; j < 8; j++)
        #pragma unroll
        for (int c = 0; c < 4; c++) o[j][c] = 0.0f;
    float mg = NEGF, m8 = NEGF, lg = 0.0f, l8 = 0.0f;

    const int srcA = (lane & ~3) | (tq >> 1);
    const int srcB = srcA + 2;
    const bool odd = (tq & 1);

    const int krr = tid >> 2;
    const int kcc = (tid & 3) * 16;
    const int ntiles = m0 / 64 + 2;

    for (int jt = 0; jt < ntiles; jt++) {
        const int t0 = jt * 64;
        {
            const float* ksrc = k + (size_t)(b * S_ + t0 + krr) * RS + h * DK_ + kcc;
            const float* vsrc = v + (size_t)(b * S_ + t0 + krr) * RS + h * DK_ + kcc;
            #pragma unroll
            for (int u = 0; u < 4; u++) {
                float4 a = *(const float4*)(ksrc + u * 4);
                float4 c = *(const float4*)(vsrc + u * 4);
                float4 at, ct;
                at.x = f2tf32f(a.x); at.y = f2tf32f(a.y); at.z = f2tf32f(a.z); at.w = f2tf32f(a.w);
                ct.x = f2tf32f(c.x); ct.y = f2tf32f(c.y); ct.z = f2tf32f(c.z); ct.w = f2tf32f(c.w);
                *(float4*)&Ks[krr * KSTR + kcc + u * 4] = at;
                *(float4*)&Vs[krr * VSTR + kcc + u * 4] = ct;
            }
        }
        __syncthreads();

        float s[8][4];
        #pragma unroll
        for (int j = 0; j < 8; j++)
            #pragma unroll
            for (int c = 0; c < 4; c++) s[j][c] = 0.0f;

        #pragma unroll
        for (int ks = 0; ks < 8; ks++) {
            #pragma unroll
            for (int jn = 0; jn < 8; jn++) {
                unsigned bf[2];
                bf[0] = __float_as_uint(Ks[(8 * jn + g) * KSTR + 8 * ks + tq]);
                bf[1] = __float_as_uint(Ks[(8 * jn + g) * KSTR + 8 * ks + tq + 4]);
                mma_tf32(s[jn], qf[ks], bf);
            }
        }

        if (t0 + 63 > m0) {
            #pragma unroll
            for (int jn = 0; jn < 8; jn++) {
                int c0 = t0 + 8 * jn + 2 * tq;
                if (c0     > r0) s[jn][0] = NEGF;
                if (c0 + 1 > r0) s[jn][1] = NEGF;
                if (c0     > r8) s[jn][2] = NEGF;
                if (c0 + 1 > r8) s[jn][3] = NEGF;
            }
        }

        float tmg = NEGF, tm8 = NEGF;
        #pragma unroll
        for (int jn = 0; jn < 8; jn++) {
            tmg = fmaxf(tmg, fmaxf(s[jn][0], s[jn][1]));
            tm8 = fmaxf(tm8, fmaxf(s[jn][2], s[jn][3]));
        }
        tmg = fmaxf(tmg, __shfl_xor_sync(0xffffffffu, tmg, 1));
        tmg = fmaxf(tmg, __shfl_xor_sync(0xffffffffu, tmg, 2));
        tm8 = fmaxf(tm8, __shfl_xor_sync(0xffffffffu, tm8, 1));
        tm8 = fmaxf(tm8, __shfl_xor_sync(0xffffffffu, tm8, 2));

        float mgn = fmaxf(mg, tmg), m8n = fmaxf(m8, tm8);
        float ag = expf(mg - mgn), a8 = expf(m8 - m8n);

        float rsg = 0.0f, rs8 = 0.0f;
        #pragma unroll
        for (int jn = 0; jn < 8; jn++) {
            s[jn][0] = expf(s[jn][0] - mgn);
            s[jn][1] = expf(s[jn][1] - mgn);
            s[jn][2] = expf(s[jn][2] - m8n);
            s[jn][3] = expf(s[jn][3] - m8n);
            rsg += s[jn][0] + s[jn][1];
            rs8 += s[jn][2] + s[jn][3];
        }
        rsg += __shfl_xor_sync(0xffffffffu, rsg, 1);
        rsg += __shfl_xor_sync(0xffffffffu, rsg, 2);
        rs8 += __shfl_xor_sync(0xffffffffu, rs8, 1);
        rs8 += __shfl_xor_sync(0xffffffffu, rs8, 2);

        lg = lg * ag + rsg;
        l8 = l8 * a8 + rs8;
        mg = mgn; m8 = m8n;

        #pragma unroll
        for (int jd = 0; jd < 8; jd++) {
            o[jd][0] *= ag; o[jd][1] *= ag;
            o[jd][2] *= a8; o[jd][3] *= a8;
        }

        #pragma unroll
        for (int kt = 0; kt < 8; kt++) {
            unsigned af[4];
            {
                float x0 = __shfl_sync(0xffffffffu, s[kt][0], srcA);
                float x1 = __shfl_sync(0xffffffffu, s[kt][1], srcA);
                float y0 = __shfl_sync(0xffffffffu, s[kt][2], srcA);
                float y1 = __shfl_sync(0xffffffffu, s[kt][3], srcA);
                float z0 = __shfl_sync(0xffffffffu, s[kt][0], srcB);
                float z1 = __shfl_sync(0xffffffffu, s[kt][1], srcB);
                float w0 = __shfl_sync(0xffffffffu, s[kt][2], srcB);
                float w1 = __shfl_sync(0xffffffffu, s[kt][3], srcB);
                af[0] = f2tf32(odd ? x1 : x0);
                af[1] = f2tf32(odd ? y1 : y0);
                af[2] = f2tf32(odd ? z1 : z0);
                af[3] = f2tf32(odd ? w1 : w0);
            }
            #pragma unroll
            for (int jd = 0; jd < 8; jd++) {
                unsigned bf[2];
                bf[0] = __float_as_uint(Vs[(8 * kt + tq) * VSTR + 8 * jd + g]);
                bf[1] = __float_as_uint(Vs[(8 * kt + tq + 4) * VSTR + 8 * jd + g]);
                mma_tf32(o[jd], af, bf);
            }
        }
        __syncthreads();
    }

    float ig = 1.0f / lg, i8 = 1.0f / l8;
    float* y0 = y + (size_t)(b * S_ + r0) * RS + h * DK_;
    float* y8 = y0 + 8 * RS;
    #pragma unroll
    for (int jd = 0; jd < 8; jd++) {
        *(float2*)(y0 + 8 * jd + 2 * tq) =
            make_float2(f2tf32f(o[jd][0] * ig), f2tf32f(o[jd][1] * ig));
        *(float2*)(y8 + 8 * jd + 2 * tq) =
            make_float2(f2tf32f(o[jd][2] * i8), f2tf32f(o[jd][3] * i8));
    }
}

// ---------------------------------------------------------------------------
// TF32 MMA GEMM: cp.async 3-stage pipeline.
// A operand pre-rounded by producers; B operand RAW fp32, rounded to tf32
// at fragment-read time (bit-identical to a prepass round).
//   BTRANS : B stored [N,K] row-major (logits: te); smem n-major
//   NGUARD : logits; grid m-fastest (blockIdx.x = m) for te L2 reuse
//   QKV    : z selects (B,bias,C) triple
//   SPLITK : z partitions K; raw partial store to C + z*M*ldc
// ---------------------------------------------------------------------------
template <bool BTRANS, bool GELU_ACT, bool NGUARD, bool QKV, int SPLITK>
__global__ void __launch_bounds__(256, 2)
mma_gemm(const float* __restrict__ Ag, const float* __restrict__ Bg,
         const float* __restrict__ biasg, float* __restrict__ Cg,
         int M, int N, int K, int lda, int ldb, int ldc,
         const float* Bg2, const float* bias2, float* Cg2,
         const float* Bg3, const float* bias3, float* Cg3)
{
    constexpr int BM = 128, BN = 128, BK = 16, STAGES = 3;
    constexpr int ASTR = 20;
    constexpr int BSTR = BTRANS ? 20 : (BN + 8);
    constexpr int ASZ  = BM * ASTR;
    constexpr int BSZ  = BTRANS ? (BN * BSTR) : (BK * BSTR);

    extern __shared__ float smem[];
    float* AsB = smem;
    float* BsB = smem + STAGES * ASZ;

    const int tid  = threadIdx.x;
    const int wid  = tid >> 5;
    const int lane = tid & 31;
    const int g    = lane >> 2;
    const int tq   = lane & 3;
    const int m0   = NGUARD ? blockIdx.x * BM : blockIdx.y * BM;
    const int n0   = NGUARD ? blockIdx.y * BN : blockIdx.x * BN;
    const int z    = blockIdx.z;

    const float* A = Ag;
    const float* B = Bg;
    const float* bias = biasg;
    float* C = Cg;

    if (QKV) {
        if (z == 1) { B = Bg2; bias = bias2; C = Cg2; }
        else if (z == 2) { B = Bg3; bias = bias3; C = Cg3; }
    } else if (SPLITK > 1) {
        C = Cg + (long long)z * M * ldc;
    }

    const int rowbase = (wid & 3) * 32;
    const int colbase = (wid >> 2) * 64;

    float acc[2][8][4];
    #pragma unroll
    for (int i = 0; i < 2; i++)
        #pragma unroll
        for (int j = 0; j < 8; j++)
            #pragma unroll
            for (int q = 0; q < 4; q++) acc[i][j][q] = 0.0f;

    int kbeg = 0, kend = K;
    if (SPLITK > 1) { kbeg = z * (K / SPLITK); kend = kbeg + K / SPLITK; }
    const int ntiles = (kend - kbeg) / BK;

    auto issue_stage = [&](int stage, int k0) {
        float* as = AsB + stage * ASZ;
        float* bs = BsB + stage * BSZ;
        #pragma unroll
        for (int i = 0; i < 2; i++) {
            int c = tid + i * 256;
            int row = c >> 2, col = (c & 3) * 4;
            cp16(&as[row * ASTR + col],
                 A + (long long)(m0 + row) * lda + k0 + col, true);
        }
        if (!BTRANS) {
            #pragma unroll
            for (int i = 0; i < 2; i++) {
                int c = tid + i * 256;
                int kr = c >> 5, nc = (c & 31) * 4;
                cp16(&bs[kr * BSTR + nc],
                     B + (long long)(k0 + kr) * ldb + n0 + nc, true);
            }
        } else {
            #pragma unroll
            for (int i = 0; i < 2; i++) {
                int c = tid + i * 256;
                int nr = c >> 2, kc = (c & 3) * 4;
                bool ok = !NGUARD || (n0 + nr) < N;
                cp16(&bs[nr * BSTR + kc],
                     B + (long long)(n0 + nr) * ldb + k0 + kc, ok);
            }
        }
        cp_commit();
    };

    issue_stage(0, kbeg);
    if (ntiles > 1) issue_stage(1, kbeg + BK);

    for (int t = 0; t < ntiles; t++) {
        if (t == ntiles - 1)
            asm volatile("cp.async.wait_group 0;\n" ::: "memory");
        else
            asm volatile("cp.async.wait_group 1;\n" ::: "memory");
        __syncthreads();

        if (t + 2 < ntiles) issue_stage((t + 2) % STAGES, kbeg + (t + 2) * BK);

        const float* as = AsB + (t % STAGES) * ASZ;
        const float* bs = BsB + (t % STAGES) * BSZ;

        #pragma unroll
        for (int ks = 0; ks < BK; ks += 8) {
            unsigned af[2][4];
            #pragma unroll
            for (int i = 0; i < 2; i++) {
                int r = rowbase + i * 16 + g;
                af[i][0] = __float_as_uint(as[r * ASTR + ks + tq]);
                af[i][1] = __float_as_uint(as[(r + 8) * ASTR + ks + tq]);
                af[i][2] = __float_as_uint(as[r * ASTR + ks + tq + 4]);
                af[i][3] = __float_as_uint(as[(r + 8) * ASTR + ks + tq + 4]);
            }
            unsigned bf[8][2];
            #pragma unroll
            for (int j = 0; j < 8; j++) {
                int c = colbase + j * 8 + g;
                if (!BTRANS) {
                    bf[j][0] = f2tf32(bs[(ks + tq) * BSTR + c]);
                    bf[j][1] = f2tf32(bs[(ks + tq + 4) * BSTR + c]);
                } else {
                    bf[j][0] = f2tf32(bs[c * BSTR + ks + tq]);
                    bf[j][1] = f2tf32(bs[c * BSTR + ks + tq + 4]);
                }
            }
            #pragma unroll
            for (int i = 0; i < 2; i++)
                #pragma unroll
                for (int j = 0; j < 8; j++)
                    mma_tf32(acc[i][j], af[i], bf[j]);
        }
    }

    // epilogue
    #pragma unroll
    for (int i = 0; i < 2; i++) {
        #pragma unroll
        for (int j = 0; j < 8; j++) {
            int r = m0 + rowbase + i * 16 + g;
            int c = n0 + colbase + j * 8 + tq * 2;
            #pragma unroll
            for (int q = 0; q < 4; q++) {
                int rr = r + (q >> 1) * 8;
                int cc = c + (q & 1);
                if (NGUARD && cc >= N) continue;
                float val = acc[i][j][q];
                if (SPLITK > 1) {
                    C[(long long)rr * ldc + cc] = val;
                } else {
                    if (bias) val += bias[cc];
                    if (GELU_ACT) val = f2tf32f(gelu_exact(val));
                    C[(long long)rr * ldc + cc] = val;
                }
            }
        }
    }
}

// ---------------------------------------------------------------------------
// Split-K reduce: x += partials + bias; also writes tf32 shadow xr
// ---------------------------------------------------------------------------
__global__ void reduce_splitk(const float* __restrict__ part,
                              const float* __restrict__ bias,
                              float* __restrict__ x, float* __restrict__ xr,
                              int NN, int ldc) {
    int idx = (blockIdx.x * 256 + threadIdx.x) * 4;
    float4 p0 = *(const float4*)(part + idx);
    float4 p1 = *(const float4*)(part + idx + NN);
    float4 xv = *(const float4*)(x + idx);
    float4 bv = *(const float4*)(bias + (idx % ldc));
    float4 o;
    o.x = xv.x + p0.x + p1.x + bv.x;
    o.y = xv.y + p0.y + p1.y + bv.y;
    o.z = xv.z + p0.z + p1.z + bv.z;
    o.w = xv.w + p0.w + p1.w + bv.w;
    *(float4*)(x + idx) = o;
    float4 r;
    r.x = f2tf32f(o.x); r.y = f2tf32f(o.y); r.z = f2tf32f(o.z); r.w = f2tf32f(o.w);
    *(float4*)(xr + idx) = r;
}

// ---------------------------------------------------------------------------
// LayerNorm: output tf32-rounded (consumed only by GEMMs)
// ---------------------------------------------------------------------------
__global__ void layernorm_kernel(const float* __restrict__ x,
                                 const float* __restrict__ g,
                                 const float* __restrict__ bb,
                                 float* __restrict__ out) {
    const int row = blockIdx.x;
    const int tid = threadIdx.x;
    const float* xr = x + (size_t)row * D_;
    __shared__ float rs[256];
    __shared__ float rq[256];

    float4 v = *(const float4*)(xr + tid * 4);
    float s  = v.x + v.y + v.z + v.w;
    float sq = v.x * v.x + v.y * v.y + v.z * v.z + v.w * v.w;
    rs[tid] = s; rq[tid] = sq;
    __syncthreads();
    for (int off = 128; off > 0; off >>= 1) {
        if (tid < off) { rs[tid] += rs[tid + off]; rq[tid] += rq[tid + off]; }
        __syncthreads();
    }
    float mu  = rs[0] * (1.0f / D_);
    float var = rq[0] * (1.0f / D_) - mu * mu;
    float rstd = rsqrtf(var + 1e-5f);

    int c = tid * 4;
    float4 gv = *(const float4*)(g + c);
    float4 bv = *(const float4*)(bb + c);
    float4 o;
    o.x = f2tf32f((v.x - mu) * rstd * gv.x + bv.x);
    o.y = f2tf32f((v.y - mu) * rstd * gv.y + bv.y);
    o.z = f2tf32f((v.z - mu) * rstd * gv.z + bv.z);
    o.w = f2tf32f((v.w - mu) * rstd * gv.w + bv.w);
    *(float4*)(out + (size_t)row * D_ + c) = o;
}

// ---------------------------------------------------------------------------
// Host launcher
// ---------------------------------------------------------------------------
extern "C" void kernel_launch(void* const* d_in, const int* in_sizes, int n_in,
                              void* d_out, int out_size) {
    const int*   idx   = (const int*)  d_in[0];
    const float* te    = (const float*)d_in[1];
    const float* pe    = (const float*)d_in[2];
    const float* wq    = (const float*)d_in[3];
    const float* bq    = (const float*)d_in[4];
    const float* wk    = (const float*)d_in[5];
    const float* bk    = (const float*)d_in[6];
    const float* wv    = (const float*)d_in[7];
    const float* bv    = (const float*)d_in[8];
    const float* wo    = (const float*)d_in[9];
    const float* bo    = (const float*)d_in[10];
    const float* ln2g  = (const float*)d_in[11];
    const float* ln2b  = (const float*)d_in[12];
    const float* w1    = (const float*)d_in[13];
    const float* b1    = (const float*)d_in[14];
    const float* w2    = (const float*)d_in[15];
    const float* b2    = (const float*)d_in[16];
    const float* lnfg  = (const float*)d_in[17];
    const float* lnfb  = (const float*)d_in[18];
    float* out = (float*)d_out;

    float *x, *xr, *q, *k, *v, *y, *ln, *h1, *p;
    cudaGetSymbolAddress((void**)&x,  g_x);
    cudaGetSymbolAddress((void**)&xr, g_xr);
    cudaGetSymbolAddress((void**)&q,  g_q);
    cudaGetSymbolAddress((void**)&k,  g_k);
    cudaGetSymbolAddress((void**)&v,  g_v);
    cudaGetSymbolAddress((void**)&y,  g_y);
    cudaGetSymbolAddress((void**)&ln, g_ln);
    cudaGetSymbolAddress((void**)&h1, g_h1);
    cudaGetSymbolAddress((void**)&p,  g_p);

    // smem sizes for pipelined GEMM
    const int ASZ = 128 * 20, BSZ_NT = 16 * 136, BSZ_T = 128 * 20;
    const size_t smem_nt = 3 * (ASZ + BSZ_NT) * sizeof(float);   // 56832
    const size_t smem_t  = 3 * (ASZ + BSZ_T) * sizeof(float);    // 61440

    auto kq  = mma_gemm<false, false, false, true,  1>;
    auto ksk = mma_gemm<false, false, false, false, 2>;
    auto kw1 = mma_gemm<false, true,  false, false, 1>;
    auto klg = mma_gemm<true,  false, true,  false, 1>;
    cudaFuncSetAttribute(kq,  cudaFuncAttributeMaxDynamicSharedMemorySize, (int)smem_nt);
    cudaFuncSetAttribute(ksk, cudaFuncAttributeMaxDynamicSharedMemorySize, (int)smem_nt);
    cudaFuncSetAttribute(kw1, cudaFuncAttributeMaxDynamicSharedMemorySize, (int)smem_nt);
    cudaFuncSetAttribute(klg, cudaFuncAttributeMaxDynamicSharedMemorySize, (int)smem_t);

    embed_kernel<<<NTOK, 256>>>(idx, te, pe, x, xr);

    const dim3 gQKV(D_ / 128, NTOK / 128, 3);
    const dim3 gSK (D_ / 128, NTOK / 128, 2);
    const dim3 gF  (DFF_ / 128, NTOK / 128);
    const dim3 gFA (S_ / 128, B_ * H_);
    const dim3 gLg (NTOK / 128, (V_ + 127) / 128);   // m fastest: te L2 reuse
    const int NN = NTOK * D_;

    for (int l = 0; l < L_; l++) {
        const float* wq_l = wq + (size_t)l * D_ * D_;
        const float* wk_l = wk + (size_t)l * D_ * D_;
        const float* wv_l = wv + (size_t)l * D_ * D_;
        const float* wo_l = wo + (size_t)l * D_ * D_;
        const float* w1_l = w1 + (size_t)l * D_ * DFF_;
        const float* w2_l = w2 + (size_t)l * DFF_ * D_;

        kq<<<gQKV, 256, smem_nt>>>(
            xr, wq_l, bq + l * D_, q, NTOK, D_, D_, D_, D_, D_,
            wk_l, bk + l * D_, k, wv_l, bv + l * D_, v);

        flash_attn<<<gFA, 256>>>(q, k, v, y);

        ksk<<<gSK, 256, smem_nt>>>(
            y, wo_l, nullptr, p, NTOK, D_, D_, D_, D_, D_,
            nullptr, nullptr, nullptr, nullptr, nullptr, nullptr);
        reduce_splitk<<<NN / 1024, 256>>>(p, bo + l * D_, x, xr, NN, D_);

        layernorm_kernel<<<NTOK, 256>>>(x, ln2g + l * D_, ln2b + l * D_, ln);

        kw1<<<gF, 256, smem_nt>>>(
            ln, w1_l, b1 + l * DFF_, h1, NTOK, DFF_, D_, D_, DFF_, DFF_,
            nullptr, nullptr, nullptr, nullptr, nullptr, nullptr);

        ksk<<<gSK, 256, smem_nt>>>(
            h1, w2_l, nullptr, p, NTOK, D_, DFF_, DFF_, D_, D_,
            nullptr, nullptr, nullptr, nullptr, nullptr, nullptr);
        reduce_splitk<<<NN / 1024, 256>>>(p, b2 + l * D_, x, xr, NN, D_);
    }

    layernorm_kernel<<<NTOK, 256>>>(x, lnfg, lnfb, ln);

    klg<<<gLg, 256, smem_t>>>(
        ln, te, nullptr, out, NTOK, V_, D_, D_, D_, V_,
        nullptr, nullptr, nullptr, nullptr, nullptr, nullptr);
}

// round 8
// speedup vs baseline: 1.8053x; 1.8053x over previous
#include <cuda_runtime.h>
#include <cuda_fp16.h>
#include <cuda_bf16.h>
#include <math.h>
#include <stdint.h>

#define D_   1024
#define H_   16
#define V_   50257
#define L_   4
#define B_   2
#define S_   1024
#define DK_  64
#define DFF_ 4096
#define NTOK (B_ * S_)
#define NEGF (-3.402823466e38f)

// ---------------------------------------------------------------------------
// Device scratch
// ---------------------------------------------------------------------------
__device__ float  g_x [NTOK * D_];          // fp32 residual master
__device__ __half g_xr[NTOK * D_];          // fp16 shadow (QKV A operand)
__device__ __half g_q [NTOK * D_];
__device__ __half g_k [NTOK * D_];
__device__ __half g_v [NTOK * D_];
__device__ __half g_y [NTOK * D_];
__device__ __half g_ln[NTOK * D_];
__device__ __half g_h1[NTOK * DFF_];
__device__ float  g_p [2 * NTOK * D_];      // split-K fp32 partials
// fp16 transposed weights [N,K] (k-contiguous) + te cast
__device__ __half g_wqT[L_ * D_ * D_];
__device__ __half g_wkT[L_ * D_ * D_];
__device__ __half g_wvT[L_ * D_ * D_];
__device__ __half g_woT[L_ * D_ * D_];
__device__ __half g_w1T[L_ * D_ * DFF_];
__device__ __half g_w2T[L_ * DFF_ * D_];
__device__ __half g_teh[(size_t)V_ * D_];

__device__ __forceinline__ float gelu_exact(float v) {
    return 0.5f * v * (1.0f + erff(v * 0.70710678118654752440f));
}

__device__ __forceinline__ void mma_f16(float* c, const unsigned* a, const unsigned* b) {
    asm volatile(
        "mma.sync.aligned.m16n8k16.row.col.f32.f16.f16.f32 "
        "{%0,%1,%2,%3},{%4,%5,%6,%7},{%8,%9},{%0,%1,%2,%3};"
        : "+f"(c[0]), "+f"(c[1]), "+f"(c[2]), "+f"(c[3])
        : "r"(a[0]), "r"(a[1]), "r"(a[2]), "r"(a[3]), "r"(b[0]), "r"(b[1]));
}
__device__ __forceinline__ void cp16(void* s, const void* g, bool pred) {
    unsigned sa = (unsigned)__cvta_generic_to_shared(s);
    int sz = pred ? 16 : 0;
    asm volatile("cp.async.cg.shared.global [%0], [%1], 16, %2;\n"
                 :: "r"(sa), "l"(g), "r"(sz));
}
__device__ __forceinline__ void cp_commit() {
    asm volatile("cp.async.commit_group;\n" ::: "memory");
}

// ---------------------------------------------------------------------------
// Prepass: transpose [K,N] fp32 -> [N,K] fp16 ; plain cast for te
// ---------------------------------------------------------------------------
__global__ void transpose_cvt(const float* __restrict__ in, __half* __restrict__ outp,
                              int K, int N) {
    __shared__ float t[32][33];
    long long zoff = (long long)blockIdx.z * K * N;
    in += zoff; outp += zoff;
    int k0 = blockIdx.y * 32, n0 = blockIdx.x * 32;
    int tx = threadIdx.x, ty = threadIdx.y;
    #pragma unroll
    for (int i = 0; i < 4; i++)
        t[ty + i * 8][tx] = in[(long long)(k0 + ty + i * 8) * N + n0 + tx];
    __syncthreads();
    #pragma unroll
    for (int i = 0; i < 4; i++)
        outp[(long long)(n0 + ty + i * 8) * K + k0 + tx] = __float2half(t[tx][ty + i * 8]);
}

__global__ void cvt_f16_kernel(const float* __restrict__ in, __half* __restrict__ outp) {
    long long i = ((long long)blockIdx.x * 256 + threadIdx.x) * 4;
    float4 v = *(const float4*)(in + i);
    *(__half2*)(outp + i)     = __floats2half2_rn(v.x, v.y);
    *(__half2*)(outp + i + 2) = __floats2half2_rn(v.z, v.w);
}

// ---------------------------------------------------------------------------
// Embedding: x fp32 + xr fp16
// ---------------------------------------------------------------------------
__global__ void embed_kernel(const int* __restrict__ idx,
                             const float* __restrict__ te,
                             const float* __restrict__ pe,
                             float* __restrict__ x, __half* __restrict__ xr) {
    int row = blockIdx.x;
    int s   = row % S_;
    int tok = idx[row];
    int c   = threadIdx.x * 4;
    float4 t = *(const float4*)(te + (size_t)tok * D_ + c);
    float4 p = *(const float4*)(pe + (size_t)s   * D_ + c);
    float4 o = make_float4(t.x + p.x, t.y + p.y, t.z + p.z, t.w + p.w);
    *(float4*)(x + (size_t)row * D_ + c) = o;
    __half* xp = xr + (size_t)row * D_ + c;
    *(__half2*)(xp)     = __floats2half2_rn(o.x, o.y);
    *(__half2*)(xp + 2) = __floats2half2_rn(o.z, o.w);
}

// ---------------------------------------------------------------------------
// Fused flash attention, fp16 MMA (m16n8k16), online softmax in fp32.
// q,k,v,y: __half [b,s,h,d]. grid (8, B*H), 256 threads (8 warps x 16 rows).
// ---------------------------------------------------------------------------
__global__ void __launch_bounds__(256, 2)
flash_attn(const __half* __restrict__ q, const __half* __restrict__ k,
           const __half* __restrict__ v, __half* __restrict__ y)
{
    // Ks: [64 t][36 half2-units]  (32 data + 4 pad); Vs: [64 d][36 units] (t-major)
    __shared__ unsigned Ksu[64 * 36];
    __shared__ __half   Vsh[64 * 72];
    unsigned* Vsu = (unsigned*)Vsh;

    const int xmap[8] = {0, 7, 1, 6, 2, 5, 3, 4};
    const int m0  = xmap[blockIdx.x] * 128;
    const int bh  = blockIdx.y;
    const int b   = bh >> 4, h = bh & 15;
    const int tid = threadIdx.x;
    const int wid = tid >> 5, lane = tid & 31;
    const int g   = lane >> 2, tq = lane & 3;
    const int r0 = m0 + wid * 16 + g;
    const int r8 = r0 + 8;
    const int RS = H_ * DK_;     // 1024 halves

    // ---- Q fragments (4 k16-steps over d=64), scaled by 1/8 (exact) ----
    unsigned qf[4][4];
    {
        const unsigned* q0u = (const unsigned*)(q + (size_t)(b * S_ + r0) * RS + h * DK_);
        const unsigned* q8u = q0u + 8 * (RS / 2);
        const __half2 sc = __float2half2_rn(0.125f);
        #pragma unroll
        for (int s = 0; s < 4; s++) {
            __half2 a0 = __hmul2(*(const __half2*)&q0u[s * 8 + tq], sc);
            __half2 a1 = __hmul2(*(const __half2*)&q8u[s * 8 + tq], sc);
            __half2 a2 = __hmul2(*(const __half2*)&q0u[s * 8 + tq + 4], sc);
            __half2 a3 = __hmul2(*(const __half2*)&q8u[s * 8 + tq + 4], sc);
            qf[s][0] = *(unsigned*)&a0; qf[s][1] = *(unsigned*)&a1;
            qf[s][2] = *(unsigned*)&a2; qf[s][3] = *(unsigned*)&a3;
        }
    }

    float o[8][4];
    #pragma unroll
    for (int j = 0; j < 8; j++)
        #pragma unroll
        for (int c = 0; c < 4; c++) o[j][c] = 0.0f;
    float mg = NEGF, m8 = NEGF, lg = 0.0f, l8 = 0.0f;

    const int ntiles = m0 / 64 + 2;

    for (int jt = 0; jt < ntiles; jt++) {
        const int t0 = jt * 64;

        // ---- load K tile 64x64 fp16 (direct copy) ----
        {
            #pragma unroll
            for (int i = 0; i < 2; i++) {
                int c = tid + i * 256;          // 0..511
                int row = c >> 3, ch = c & 7;   // 8 x 16B chunks per row
                uint4 kv = *(const uint4*)(k + (size_t)(b * S_ + t0 + row) * RS
                                           + h * DK_ + ch * 8);
                *(uint4*)&Ksu[row * 36 + ch * 4] = kv;
            }
            // ---- V tile transposed: Vs[d][t] ----
            int t = tid >> 2;                   // 0..63
            int dc = (tid & 3) * 16;            // d chunk of 16
            const __half* vsrc = v + (size_t)(b * S_ + t0 + t) * RS + h * DK_ + dc;
            uint4 v0 = *(const uint4*)(vsrc);
            uint4 v1 = *(const uint4*)(vsrc + 8);
            const __half* vh0 = (const __half*)&v0;
            const __half* vh1 = (const __half*)&v1;
            #pragma unroll
            for (int i = 0; i < 8; i++) {
                Vsh[(dc + i) * 72 + t]     = vh0[i];
                Vsh[(dc + 8 + i) * 72 + t] = vh1[i];
            }
        }
        __syncthreads();

        // ---- S = (Q/8) @ K^T : 4 ksteps x 8 n-tiles ----
        float s[8][4];
        #pragma unroll
        for (int j = 0; j < 8; j++)
            #pragma unroll
            for (int c = 0; c < 4; c++) s[j][c] = 0.0f;

        #pragma unroll
        for (int ks = 0; ks < 4; ks++) {
            #pragma unroll
            for (int jn = 0; jn < 8; jn++) {
                unsigned bf[2];
                bf[0] = Ksu[(8 * jn + g) * 36 + 8 * ks + tq];
                bf[1] = Ksu[(8 * jn + g) * 36 + 8 * ks + tq + 4];
                mma_f16(s[jn], qf[ks], bf);
            }
        }

        // ---- causal mask ----
        if (t0 + 63 > m0) {
            #pragma unroll
            for (int jn = 0; jn < 8; jn++) {
                int c0 = t0 + 8 * jn + 2 * tq;
                if (c0     > r0) s[jn][0] = NEGF;
                if (c0 + 1 > r0) s[jn][1] = NEGF;
                if (c0     > r8) s[jn][2] = NEGF;
                if (c0 + 1 > r8) s[jn][3] = NEGF;
            }
        }

        // ---- online softmax (fp32) ----
        float tmg = NEGF, tm8 = NEGF;
        #pragma unroll
        for (int jn = 0; jn < 8; jn++) {
            tmg = fmaxf(tmg, fmaxf(s[jn][0], s[jn][1]));
            tm8 = fmaxf(tm8, fmaxf(s[jn][2], s[jn][3]));
        }
        tmg = fmaxf(tmg, __shfl_xor_sync(0xffffffffu, tmg, 1));
        tmg = fmaxf(tmg, __shfl_xor_sync(0xffffffffu, tmg, 2));
        tm8 = fmaxf(tm8, __shfl_xor_sync(0xffffffffu, tm8, 1));
        tm8 = fmaxf(tm8, __shfl_xor_sync(0xffffffffu, tm8, 2));

        float mgn = fmaxf(mg, tmg), m8n = fmaxf(m8, tm8);
        float ag = expf(mg - mgn), a8 = expf(m8 - m8n);

        float rsg = 0.0f, rs8 = 0.0f;
        #pragma unroll
        for (int jn = 0; jn < 8; jn++) {
            s[jn][0] = expf(s[jn][0] - mgn);
            s[jn][1] = expf(s[jn][1] - mgn);
            s[jn][2] = expf(s[jn][2] - m8n);
            s[jn][3] = expf(s[jn][3] - m8n);
            rsg += s[jn][0] + s[jn][1];
            rs8 += s[jn][2] + s[jn][3];
        }
        rsg += __shfl_xor_sync(0xffffffffu, rsg, 1);
        rsg += __shfl_xor_sync(0xffffffffu, rsg, 2);
        rs8 += __shfl_xor_sync(0xffffffffu, rs8, 1);
        rs8 += __shfl_xor_sync(0xffffffffu, rs8, 2);

        lg = lg * ag + rsg;
        l8 = l8 * a8 + rs8;
        mg = mgn; m8 = m8n;

        #pragma unroll
        for (int jd = 0; jd < 8; jd++) {
            o[jd][0] *= ag; o[jd][1] *= ag;
            o[jd][2] *= a8; o[jd][3] *= a8;
        }

        // ---- O += P @ V : P fragments come straight from the S C-layout ----
        #pragma unroll
        for (int u = 0; u < 4; u++) {          // k16 window over t
            unsigned af[4];
            __half2 p0 = __floats2half2_rn(s[2 * u][0], s[2 * u][1]);
            __half2 p1 = __floats2half2_rn(s[2 * u][2], s[2 * u][3]);
            __half2 p2 = __floats2half2_rn(s[2 * u + 1][0], s[2 * u + 1][1]);
            __half2 p3 = __floats2half2_rn(s[2 * u + 1][2], s[2 * u + 1][3]);
            af[0] = *(unsigned*)&p0; af[1] = *(unsigned*)&p1;
            af[2] = *(unsigned*)&p2; af[3] = *(unsigned*)&p3;
            #pragma unroll
            for (int jd = 0; jd < 8; jd++) {
                unsigned bf[2];
                bf[0] = Vsu[(8 * jd + g) * 36 + 8 * u + tq];
                bf[1] = Vsu[(8 * jd + g) * 36 + 8 * u + tq + 4];
                mma_f16(o[jd], af, bf);
            }
        }
        __syncthreads();
    }

    // ---- normalize + write fp16 y ----
    float ig = 1.0f / lg, i8 = 1.0f / l8;
    __half* y0 = y + (size_t)(b * S_ + r0) * RS + h * DK_;
    __half* y8 = y0 + 8 * RS;
    #pragma unroll
    for (int jd = 0; jd < 8; jd++) {
        *(__half2*)(y0 + 8 * jd + 2 * tq) =
            __floats2half2_rn(o[jd][0] * ig, o[jd][1] * ig);
        *(__half2*)(y8 + 8 * jd + 2 * tq) =
            __floats2half2_rn(o[jd][2] * i8, o[jd][3] * i8);
    }
}

// ---------------------------------------------------------------------------
// FP16 MMA GEMM: cp.async 3-stage pipeline, BK=32 fp16, all B operands [N,K].
//   CT      : output type (__half for qkv/h1, float for splitK/logits)
//   NGUARD  : logits (m on blockIdx.x for te L2 reuse, per-element N guard)
//   QKV     : z selects (B,bias,C) triple
//   SPLITK  : z partitions K; raw fp32 partial store
// BM=BN=128, 256 threads, warp tile 32x64.
// ---------------------------------------------------------------------------
template <typename CT, bool GELU_ACT, bool QKV, int SPLITK, bool NGUARD>
__global__ void __launch_bounds__(256, 2)
mma_gemm(const __half* __restrict__ Ag, const __half* __restrict__ Bg,
         const float* __restrict__ biasg, CT* __restrict__ Cg,
         int M, int N, int K, int lda, int ldb, int ldc,
         const __half* Bg2, const float* bias2, CT* Cg2,
         const __half* Bg3, const float* bias3, CT* Cg3)
{
    constexpr int BM = 128, BK = 32, STAGES = 3;   // BK in fp16 elements
    constexpr int STR = 20;                        // stride in half2 units
    constexpr int TSZ = BM * STR;                  // per-stage units (A or B)

    extern __shared__ unsigned smem_u[];
    unsigned* AsB = smem_u;
    unsigned* BsB = smem_u + STAGES * TSZ;

    const int tid  = threadIdx.x;
    const int wid  = tid >> 5;
    const int lane = tid & 31;
    const int g    = lane >> 2;
    const int tq   = lane & 3;
    const int m0   = NGUARD ? blockIdx.x * BM : blockIdx.y * BM;
    const int n0   = NGUARD ? blockIdx.y * BM : blockIdx.x * BM;
    const int z    = blockIdx.z;

    const __half* A = Ag;
    const __half* B = Bg;
    const float* bias = biasg;
    CT* C = Cg;

    if (QKV) {
        if (z == 1) { B = Bg2; bias = bias2; C = Cg2; }
        else if (z == 2) { B = Bg3; bias = bias3; C = Cg3; }
    } else if (SPLITK > 1) {
        C = Cg + (long long)z * M * ldc;
    }

    const int rowbase = (wid & 3) * 32;
    const int colbase = (wid >> 2) * 64;

    float acc[2][8][4];
    #pragma unroll
    for (int i = 0; i < 2; i++)
        #pragma unroll
        for (int j = 0; j < 8; j++)
            #pragma unroll
            for (int qq = 0; qq < 4; qq++) acc[i][j][qq] = 0.0f;

    int kbeg = 0, kend = K;
    if (SPLITK > 1) { kbeg = z * (K / SPLITK); kend = kbeg + K / SPLITK; }
    const int ntiles = (kend - kbeg) / BK;

    auto issue_stage = [&](int stage, int k0) {
        unsigned* as = AsB + stage * TSZ;
        unsigned* bs = BsB + stage * TSZ;
        #pragma unroll
        for (int i = 0; i < 2; i++) {
            int c = tid + i * 256;              // 512 chunks of 16B (128 rows x 4)
            int row = c >> 2, ch = c & 3;
            cp16(&as[row * STR + ch * 4],
                 A + (long long)(m0 + row) * lda + k0 + ch * 8, true);
        }
        #pragma unroll
        for (int i = 0; i < 2; i++) {
            int c = tid + i * 256;
            int row = c >> 2, ch = c & 3;
            bool ok = !NGUARD || (n0 + row) < N;
            cp16(&bs[row * STR + ch * 4],
                 B + (long long)(n0 + row) * ldb + k0 + ch * 8, ok);
        }
        cp_commit();
    };

    issue_stage(0, kbeg);
    if (ntiles > 1) issue_stage(1, kbeg + BK);

    for (int t = 0; t < ntiles; t++) {
        if (t == ntiles - 1)
            asm volatile("cp.async.wait_group 0;\n" ::: "memory");
        else
            asm volatile("cp.async.wait_group 1;\n" ::: "memory");
        __syncthreads();

        if (t + 2 < ntiles) issue_stage((t + 2) % STAGES, kbeg + (t + 2) * BK);

        const unsigned* as = AsB + (t % STAGES) * TSZ;
        const unsigned* bs = BsB + (t % STAGES) * TSZ;

        #pragma unroll
        for (int ks = 0; ks < 16; ks += 8) {   // two k16-steps per BK=32 tile
            unsigned af[2][4];
            #pragma unroll
            for (int i = 0; i < 2; i++) {
                int r = rowbase + i * 16 + g;
                af[i][0] = as[r * STR + ks + tq];
                af[i][1] = as[(r + 8) * STR + ks + tq];
                af[i][2] = as[r * STR + ks + tq + 4];
                af[i][3] = as[(r + 8) * STR + ks + tq + 4];
            }
            unsigned bf[8][2];
            #pragma unroll
            for (int j = 0; j < 8; j++) {
                int c = colbase + j * 8 + g;
                bf[j][0] = bs[c * STR + ks + tq];
                bf[j][1] = bs[c * STR + ks + tq + 4];
            }
            #pragma unroll
            for (int i = 0; i < 2; i++)
                #pragma unroll
                for (int j = 0; j < 8; j++)
                    mma_f16(acc[i][j], af[i], bf[j]);
        }
    }

    // ---- epilogue ----
    #pragma unroll
    for (int i = 0; i < 2; i++) {
        #pragma unroll
        for (int j = 0; j < 8; j++) {
            int r = m0 + rowbase + i * 16 + g;
            int c = n0 + colbase + j * 8 + tq * 2;
            #pragma unroll
            for (int hh = 0; hh < 2; hh++) {
                int rr = r + hh * 8;
                float v0 = acc[i][j][hh * 2 + 0];
                float v1 = acc[i][j][hh * 2 + 1];
                if constexpr (SPLITK > 1) {
                    *(float2*)((float*)C + (long long)rr * ldc + c) = make_float2(v0, v1);
                } else {
                    if (bias) { v0 += bias[c]; v1 += bias[c + 1]; }
                    if (GELU_ACT) { v0 = gelu_exact(v0); v1 = gelu_exact(v1); }
                    if constexpr (NGUARD) {
                        float* Cf = (float*)C;
                        if (c < N)     Cf[(long long)rr * ldc + c]     = v0;
                        if (c + 1 < N) Cf[(long long)rr * ldc + c + 1] = v1;
                    } else if constexpr (sizeof(CT) == 2) {
                        *(__half2*)((__half*)C + (long long)rr * ldc + c) =
                            __floats2half2_rn(v0, v1);
                    } else {
                        *(float2*)((float*)C + (long long)rr * ldc + c) =
                            make_float2(v0, v1);
                    }
                }
            }
        }
    }
}

// ---------------------------------------------------------------------------
// Split-K reduce: x += partials + bias; writes fp16 shadow xr
// ---------------------------------------------------------------------------
__global__ void reduce_splitk(const float* __restrict__ part,
                              const float* __restrict__ bias,
                              float* __restrict__ x, __half* __restrict__ xr,
                              int NN, int ldc) {
    int idx = (blockIdx.x * 256 + threadIdx.x) * 4;
    float4 p0 = *(const float4*)(part + idx);
    float4 p1 = *(const float4*)(part + idx + NN);
    float4 xv = *(const float4*)(x + idx);
    float4 bv = *(const float4*)(bias + (idx % ldc));
    float4 o;
    o.x = xv.x + p0.x + p1.x + bv.x;
    o.y = xv.y + p0.y + p1.y + bv.y;
    o.z = xv.z + p0.z + p1.z + bv.z;
    o.w = xv.w + p0.w + p1.w + bv.w;
    *(float4*)(x + idx) = o;
    *(__half2*)(xr + idx)     = __floats2half2_rn(o.x, o.y);
    *(__half2*)(xr + idx + 2) = __floats2half2_rn(o.z, o.w);
}

// ---------------------------------------------------------------------------
// LayerNorm: fp32 in, fp16 out (GEMM A operand)
// ---------------------------------------------------------------------------
__global__ void layernorm_kernel(const float* __restrict__ x,
                                 const float* __restrict__ g,
                                 const float* __restrict__ bb,
                                 __half* __restrict__ outp) {
    const int row = blockIdx.x;
    const int tid = threadIdx.x;
    const float* xr = x + (size_t)row * D_;
    __shared__ float rs[256];
    __shared__ float rq[256];

    float4 v = *(const float4*)(xr + tid * 4);
    float s  = v.x + v.y + v.z + v.w;
    float sq = v.x * v.x + v.y * v.y + v.z * v.z + v.w * v.w;
    rs[tid] = s; rq[tid] = sq;
    __syncthreads();
    for (int off = 128; off > 0; off >>= 1) {
        if (tid < off) { rs[tid] += rs[tid + off]; rq[tid] += rq[tid + off]; }
        __syncthreads();
    }
    float mu  = rs[0] * (1.0f / D_);
    float var = rq[0] * (1.0f / D_) - mu * mu;
    float rstd = rsqrtf(var + 1e-5f);

    int c = tid * 4;
    float4 gv = *(const float4*)(g + c);
    float4 bv = *(const float4*)(bb + c);
    float o0 = (v.x - mu) * rstd * gv.x + bv.x;
    float o1 = (v.y - mu) * rstd * gv.y + bv.y;
    float o2 = (v.z - mu) * rstd * gv.z + bv.z;
    float o3 = (v.w - mu) * rstd * gv.w + bv.w;
    __half* op = outp + (size_t)row * D_ + c;
    *(__half2*)(op)     = __floats2half2_rn(o0, o1);
    *(__half2*)(op + 2) = __floats2half2_rn(o2, o3);
}

// ---------------------------------------------------------------------------
// Host launcher
// ---------------------------------------------------------------------------
extern "C" void kernel_launch(void* const* d_in, const int* in_sizes, int n_in,
                              void* d_out, int out_size) {
    const int*   idx   = (const int*)  d_in[0];
    const float* te    = (const float*)d_in[1];
    const float* pe    = (const float*)d_in[2];
    const float* wq    = (const float*)d_in[3];
    const float* bq    = (const float*)d_in[4];
    const float* wk    = (const float*)d_in[5];
    const float* bk    = (const float*)d_in[6];
    const float* wv    = (const float*)d_in[7];
    const float* bv    = (const float*)d_in[8];
    const float* wo    = (const float*)d_in[9];
    const float* bo    = (const float*)d_in[10];
    const float* ln2g  = (const float*)d_in[11];
    const float* ln2b  = (const float*)d_in[12];
    const float* w1    = (const float*)d_in[13];
    const float* b1    = (const float*)d_in[14];
    const float* w2    = (const float*)d_in[15];
    const float* b2    = (const float*)d_in[16];
    const float* lnfg  = (const float*)d_in[17];
    const float* lnfb  = (const float*)d_in[18];
    float* out = (float*)d_out;

    float *x, *p;
    __half *xr, *q, *k, *v, *y, *ln, *h1;
    __half *wqT, *wkT, *wvT, *woT, *w1T, *w2T, *teh;
    cudaGetSymbolAddress((void**)&x,  g_x);
    cudaGetSymbolAddress((void**)&xr, g_xr);
    cudaGetSymbolAddress((void**)&q,  g_q);
    cudaGetSymbolAddress((void**)&k,  g_k);
    cudaGetSymbolAddress((void**)&v,  g_v);
    cudaGetSymbolAddress((void**)&y,  g_y);
    cudaGetSymbolAddress((void**)&ln, g_ln);
    cudaGetSymbolAddress((void**)&h1, g_h1);
    cudaGetSymbolAddress((void**)&p,  g_p);
    cudaGetSymbolAddress((void**)&wqT, g_wqT);
    cudaGetSymbolAddress((void**)&wkT, g_wkT);
    cudaGetSymbolAddress((void**)&wvT, g_wvT);
    cudaGetSymbolAddress((void**)&woT, g_woT);
    cudaGetSymbolAddress((void**)&w1T, g_w1T);
    cudaGetSymbolAddress((void**)&w2T, g_w2T);
    cudaGetSymbolAddress((void**)&teh, g_teh);

    // smem: 3 stages x (A 10240B + B 10240B) = 61440B
    const size_t smem_sz = 3 * 2 * 128 * 20 * 4;

    auto kq  = mma_gemm<__half, false, true,  1, false>;
    auto ksk = mma_gemm<float,  false, false, 2, false>;
    auto kw1 = mma_gemm<__half, true,  false, 1, false>;
    auto klg = mma_gemm<float,  false, false, 1, true>;
    cudaFuncSetAttribute(kq,  cudaFuncAttributeMaxDynamicSharedMemorySize, (int)smem_sz);
    cudaFuncSetAttribute(ksk, cudaFuncAttributeMaxDynamicSharedMemorySize, (int)smem_sz);
    cudaFuncSetAttribute(kw1, cudaFuncAttributeMaxDynamicSharedMemorySize, (int)smem_sz);
    cudaFuncSetAttribute(klg, cudaFuncAttributeMaxDynamicSharedMemorySize, (int)smem_sz);

    // ---- prepass: transpose+cast weights to [N,K] fp16; cast te ----
    dim3 tb(32, 8);
    transpose_cvt<<<dim3(32, 32, L_), tb>>>(wq, wqT, D_, D_);
    transpose_cvt<<<dim3(32, 32, L_), tb>>>(wk, wkT, D_, D_);
    transpose_cvt<<<dim3(32, 32, L_), tb>>>(wv, wvT, D_, D_);
    transpose_cvt<<<dim3(32, 32, L_), tb>>>(wo, woT, D_, D_);
    transpose_cvt<<<dim3(DFF_ / 32, D_ / 32, L_), tb>>>(w1, w1T, D_, DFF_);
    transpose_cvt<<<dim3(D_ / 32, DFF_ / 32, L_), tb>>>(w2, w2T, DFF_, D_);
    cvt_f16_kernel<<<V_ * (D_ / 1024), 256>>>(te, teh);

    embed_kernel<<<NTOK, 256>>>(idx, te, pe, x, xr);

    const dim3 gQKV(D_ / 128, NTOK / 128, 3);
    const dim3 gSK (D_ / 128, NTOK / 128, 2);
    const dim3 gF  (DFF_ / 128, NTOK / 128);
    const dim3 gFA (S_ / 128, B_ * H_);
    const dim3 gLg (NTOK / 128, (V_ + 127) / 128);   // m fastest: te L2 reuse
    const int NN = NTOK * D_;

    for (int l = 0; l < L_; l++) {
        const __half* wq_l = wqT + (size_t)l * D_ * D_;
        const __half* wk_l = wkT + (size_t)l * D_ * D_;
        const __half* wv_l = wvT + (size_t)l * D_ * D_;
        const __half* wo_l = woT + (size_t)l * D_ * D_;
        const __half* w1_l = w1T + (size_t)l * D_ * DFF_;
        const __half* w2_l = w2T + (size_t)l * DFF_ * D_;

        // q/k/v = xr @ W^T + b (fused over z)
        kq<<<gQKV, 256, smem_sz>>>(
            xr, wq_l, bq + l * D_, q, NTOK, D_, D_, D_, D_, D_,
            wk_l, bk + l * D_, k, wv_l, bv + l * D_, v);

        flash_attn<<<gFA, 256>>>(q, k, v, y);

        // x += y @ wo^T + bo (split-K2)
        ksk<<<gSK, 256, smem_sz>>>(
            y, wo_l, nullptr, p, NTOK, D_, D_, D_, D_, D_,
            nullptr, nullptr, nullptr, nullptr, nullptr, nullptr);
        reduce_splitk<<<NN / 1024, 256>>>(p, bo + l * D_, x, xr, NN, D_);

        layernorm_kernel<<<NTOK, 256>>>(x, ln2g + l * D_, ln2b + l * D_, ln);

        // h1 = gelu(ln @ w1^T + b1)
        kw1<<<gF, 256, smem_sz>>>(
            ln, w1_l, b1 + l * DFF_, h1, NTOK, DFF_, D_, D_, D_, DFF_,
            nullptr, nullptr, nullptr, nullptr, nullptr, nullptr);

        // x += h1 @ w2^T + b2 (split-K2)
        ksk<<<gSK, 256, smem_sz>>>(
            h1, w2_l, nullptr, p, NTOK, D_, DFF_, DFF_, DFF_, D_,
            nullptr, nullptr, nullptr, nullptr, nullptr, nullptr);
        reduce_splitk<<<NN / 1024, 256>>>(p, b2 + l * D_, x, xr, NN, D_);
    }

    layernorm_kernel<<<NTOK, 256>>>(x, lnfg, lnfb, ln);

    // logits = ln @ te^T (te already [V, K])
    klg<<<gLg, 256, smem_sz>>>(
        ln, teh, nullptr, out, NTOK, V_, D_, D_, D_, V_,
        nullptr, nullptr, nullptr, nullptr, nullptr, nullptr);
}

// round 9
// speedup vs baseline: 1.8069x; 1.0009x over previous
#include <cuda_runtime.h>
#include <cuda_fp16.h>
#include <cuda_bf16.h>
#include <math.h>
#include <stdint.h>

#define D_   1024
#define H_   16
#define V_   50257
#define L_   4
#define B_   2
#define S_   1024
#define DK_  64
#define DFF_ 4096
#define NTOK (B_ * S_)
#define NEGF (-3.402823466e38f)

// ---------------------------------------------------------------------------
// Device scratch
// ---------------------------------------------------------------------------
__device__ float  g_x [NTOK * D_];
__device__ __half g_xr[NTOK * D_];
__device__ __half g_q [NTOK * D_];
__device__ __half g_k [NTOK * D_];
__device__ __half g_v [NTOK * D_];
__device__ __half g_y [NTOK * D_];
__device__ __half g_ln[NTOK * D_];
__device__ __half g_h1[NTOK * DFF_];
__device__ float  g_p [2 * NTOK * D_];
__device__ __half g_wqT[L_ * D_ * D_];
__device__ __half g_wkT[L_ * D_ * D_];
__device__ __half g_wvT[L_ * D_ * D_];
__device__ __half g_woT[L_ * D_ * D_];
__device__ __half g_w1T[L_ * D_ * DFF_];
__device__ __half g_w2T[L_ * DFF_ * D_];
__device__ __half g_teh[(size_t)V_ * D_];

__device__ __forceinline__ float gelu_exact(float v) {
    return 0.5f * v * (1.0f + erff(v * 0.70710678118654752440f));
}

__device__ __forceinline__ void mma_f16(float* c, const unsigned* a, const unsigned* b) {
    asm volatile(
        "mma.sync.aligned.m16n8k16.row.col.f32.f16.f16.f32 "
        "{%0,%1,%2,%3},{%4,%5,%6,%7},{%8,%9},{%0,%1,%2,%3};"
        : "+f"(c[0]), "+f"(c[1]), "+f"(c[2]), "+f"(c[3])
        : "r"(a[0]), "r"(a[1]), "r"(a[2]), "r"(a[3]), "r"(b[0]), "r"(b[1]));
}
__device__ __forceinline__ void ldsm4(unsigned* r, uint32_t addr) {
    asm volatile("ldmatrix.sync.aligned.m8n8.x4.shared.b16 {%0,%1,%2,%3}, [%4];"
        : "=r"(r[0]), "=r"(r[1]), "=r"(r[2]), "=r"(r[3]) : "r"(addr));
}
__device__ __forceinline__ void cp16(void* s, const void* g, bool pred) {
    unsigned sa = (unsigned)__cvta_generic_to_shared(s);
    int sz = pred ? 16 : 0;
    asm volatile("cp.async.cg.shared.global [%0], [%1], 16, %2;\n"
                 :: "r"(sa), "l"(g), "r"(sz));
}
__device__ __forceinline__ void cp_commit() {
    asm volatile("cp.async.commit_group;\n" ::: "memory");
}

// ---------------------------------------------------------------------------
// Prepass: transpose [K,N] fp32 -> [N,K] fp16 ; wide cast for te
// ---------------------------------------------------------------------------
__global__ void transpose_cvt(const float* __restrict__ in, __half* __restrict__ outp,
                              int K, int N) {
    __shared__ float t[32][33];
    long long zoff = (long long)blockIdx.z * K * N;
    in += zoff; outp += zoff;
    int k0 = blockIdx.y * 32, n0 = blockIdx.x * 32;
    int tx = threadIdx.x, ty = threadIdx.y;
    #pragma unroll
    for (int i = 0; i < 4; i++)
        t[ty + i * 8][tx] = in[(long long)(k0 + ty + i * 8) * N + n0 + tx];
    __syncthreads();
    #pragma unroll
    for (int i = 0; i < 4; i++)
        outp[(long long)(n0 + ty + i * 8) * K + k0 + tx] = __float2half(t[tx][ty + i * 8]);
}

__global__ void cvt_f16_kernel(const float* __restrict__ in, __half* __restrict__ outp,
                               long long NTOTAL) {
    long long i = ((long long)blockIdx.x * 256 + threadIdx.x) * 8;
    if (i + 8 <= NTOTAL) {
        float4 v0 = *(const float4*)(in + i);
        float4 v1 = *(const float4*)(in + i + 4);
        __half2 h0 = __floats2half2_rn(v0.x, v0.y);
        __half2 h1 = __floats2half2_rn(v0.z, v0.w);
        __half2 h2 = __floats2half2_rn(v1.x, v1.y);
        __half2 h3 = __floats2half2_rn(v1.z, v1.w);
        uint4 pk;
        pk.x = *(unsigned*)&h0; pk.y = *(unsigned*)&h1;
        pk.z = *(unsigned*)&h2; pk.w = *(unsigned*)&h3;
        *(uint4*)(outp + i) = pk;
    } else {
        for (long long e = i; e < NTOTAL; e++) outp[e] = __float2half(in[e]);
    }
}

// ---------------------------------------------------------------------------
// Embedding: x fp32 + xr fp16
// ---------------------------------------------------------------------------
__global__ void embed_kernel(const int* __restrict__ idx,
                             const float* __restrict__ te,
                             const float* __restrict__ pe,
                             float* __restrict__ x, __half* __restrict__ xr) {
    int row = blockIdx.x;
    int s   = row % S_;
    int tok = idx[row];
    int c   = threadIdx.x * 4;
    float4 t = *(const float4*)(te + (size_t)tok * D_ + c);
    float4 p = *(const float4*)(pe + (size_t)s   * D_ + c);
    float4 o = make_float4(t.x + p.x, t.y + p.y, t.z + p.z, t.w + p.w);
    *(float4*)(x + (size_t)row * D_ + c) = o;
    __half* xp = xr + (size_t)row * D_ + c;
    *(__half2*)(xp)     = __floats2half2_rn(o.x, o.y);
    *(__half2*)(xp + 2) = __floats2half2_rn(o.z, o.w);
}

// ---------------------------------------------------------------------------
// Fused flash attention, fp16 MMA (unchanged from R8)
// ---------------------------------------------------------------------------
__global__ void __launch_bounds__(256, 2)
flash_attn(const __half* __restrict__ q, const __half* __restrict__ k,
           const __half* __restrict__ v, __half* __restrict__ y)
{
    __shared__ unsigned Ksu[64 * 36];
    __shared__ __half   Vsh[64 * 72];
    unsigned* Vsu = (unsigned*)Vsh;

    const int xmap[8] = {0, 7, 1, 6, 2, 5, 3, 4};
    const int m0  = xmap[blockIdx.x] * 128;
    const int bh  = blockIdx.y;
    const int b   = bh >> 4, h = bh & 15;
    const int tid = threadIdx.x;
    const int wid = tid >> 5, lane = tid & 31;
    const int g   = lane >> 2, tq = lane & 3;
    const int r0 = m0 + wid * 16 + g;
    const int r8 = r0 + 8;
    const int RS = H_ * DK_;

    unsigned qf[4][4];
    {
        const unsigned* q0u = (const unsigned*)(q + (size_t)(b * S_ + r0) * RS + h * DK_);
        const unsigned* q8u = q0u + 8 * (RS / 2);
        const __half2 sc = __float2half2_rn(0.125f);
        #pragma unroll
        for (int s = 0; s < 4; s++) {
            __half2 a0 = __hmul2(*(const __half2*)&q0u[s * 8 + tq], sc);
            __half2 a1 = __hmul2(*(const __half2*)&q8u[s * 8 + tq], sc);
            __half2 a2 = __hmul2(*(const __half2*)&q0u[s * 8 + tq + 4], sc);
            __half2 a3 = __hmul2(*(const __half2*)&q8u[s * 8 + tq + 4], sc);
            qf[s][0] = *(unsigned*)&a0; qf[s][1] = *(unsigned*)&a1;
            qf[s][2] = *(unsigned*)&a2; qf[s][3] = *(unsigned*)&a3;
        }
    }

    float o[8][4];
    #pragma unroll
    for (int j = 0; j < 8; j++)
        #pragma unroll
        for (int c = 0; c < 4; c++) o[j][c] = 0.0f;
    float mg = NEGF, m8 = NEGF, lg = 0.0f, l8 = 0.0f;

    const int ntiles = m0 / 64 + 2;

    for (int jt = 0; jt < ntiles; jt++) {
        const int t0 = jt * 64;
        {
            #pragma unroll
            for (int i = 0; i < 2; i++) {
                int c = tid + i * 256;
                int row = c >> 3, ch = c & 7;
                uint4 kv = *(const uint4*)(k + (size_t)(b * S_ + t0 + row) * RS
                                           + h * DK_ + ch * 8);
                *(uint4*)&Ksu[row * 36 + ch * 4] = kv;
            }
            int t = tid >> 2;
            int dc = (tid & 3) * 16;
            const __half* vsrc = v + (size_t)(b * S_ + t0 + t) * RS + h * DK_ + dc;
            uint4 v0 = *(const uint4*)(vsrc);
            uint4 v1 = *(const uint4*)(vsrc + 8);
            const __half* vh0 = (const __half*)&v0;
            const __half* vh1 = (const __half*)&v1;
            #pragma unroll
            for (int i = 0; i < 8; i++) {
                Vsh[(dc + i) * 72 + t]     = vh0[i];
                Vsh[(dc + 8 + i) * 72 + t] = vh1[i];
            }
        }
        __syncthreads();

        float s[8][4];
        #pragma unroll
        for (int j = 0; j < 8; j++)
            #pragma unroll
            for (int c = 0; c < 4; c++) s[j][c] = 0.0f;

        #pragma unroll
        for (int ks = 0; ks < 4; ks++) {
            #pragma unroll
            for (int jn = 0; jn < 8; jn++) {
                unsigned bf[2];
                bf[0] = Ksu[(8 * jn + g) * 36 + 8 * ks + tq];
                bf[1] = Ksu[(8 * jn + g) * 36 + 8 * ks + tq + 4];
                mma_f16(s[jn], qf[ks], bf);
            }
        }

        if (t0 + 63 > m0) {
            #pragma unroll
            for (int jn = 0; jn < 8; jn++) {
                int c0 = t0 + 8 * jn + 2 * tq;
                if (c0     > r0) s[jn][0] = NEGF;
                if (c0 + 1 > r0) s[jn][1] = NEGF;
                if (c0     > r8) s[jn][2] = NEGF;
                if (c0 + 1 > r8) s[jn][3] = NEGF;
            }
        }

        float tmg = NEGF, tm8 = NEGF;
        #pragma unroll
        for (int jn = 0; jn < 8; jn++) {
            tmg = fmaxf(tmg, fmaxf(s[jn][0], s[jn][1]));
            tm8 = fmaxf(tm8, fmaxf(s[jn][2], s[jn][3]));
        }
        tmg = fmaxf(tmg, __shfl_xor_sync(0xffffffffu, tmg, 1));
        tmg = fmaxf(tmg, __shfl_xor_sync(0xffffffffu, tmg, 2));
        tm8 = fmaxf(tm8, __shfl_xor_sync(0xffffffffu, tm8, 1));
        tm8 = fmaxf(tm8, __shfl_xor_sync(0xffffffffu, tm8, 2));

        float mgn = fmaxf(mg, tmg), m8n = fmaxf(m8, tm8);
        float ag = expf(mg - mgn), a8 = expf(m8 - m8n);

        float rsg = 0.0f, rs8 = 0.0f;
        #pragma unroll
        for (int jn = 0; jn < 8; jn++) {
            s[jn][0] = expf(s[jn][0] - mgn);
            s[jn][1] = expf(s[jn][1] - mgn);
            s[jn][2] = expf(s[jn][2] - m8n);
            s[jn][3] = expf(s[jn][3] - m8n);
            rsg += s[jn][0] + s[jn][1];
            rs8 += s[jn][2] + s[jn][3];
        }
        rsg += __shfl_xor_sync(0xffffffffu, rsg, 1);
        rsg += __shfl_xor_sync(0xffffffffu, rsg, 2);
        rs8 += __shfl_xor_sync(0xffffffffu, rs8, 1);
        rs8 += __shfl_xor_sync(0xffffffffu, rs8, 2);

        lg = lg * ag + rsg;
        l8 = l8 * a8 + rs8;
        mg = mgn; m8 = m8n;

        #pragma unroll
        for (int jd = 0; jd < 8; jd++) {
            o[jd][0] *= ag; o[jd][1] *= ag;
            o[jd][2] *= a8; o[jd][3] *= a8;
        }

        #pragma unroll
        for (int u = 0; u < 4; u++) {
            unsigned af[4];
            __half2 p0 = __floats2half2_rn(s[2 * u][0], s[2 * u][1]);
            __half2 p1 = __floats2half2_rn(s[2 * u][2], s[2 * u][3]);
            __half2 p2 = __floats2half2_rn(s[2 * u + 1][0], s[2 * u + 1][1]);
            __half2 p3 = __floats2half2_rn(s[2 * u + 1][2], s[2 * u + 1][3]);
            af[0] = *(unsigned*)&p0; af[1] = *(unsigned*)&p1;
            af[2] = *(unsigned*)&p2; af[3] = *(unsigned*)&p3;
            #pragma unroll
            for (int jd = 0; jd < 8; jd++) {
                unsigned bf[2];
                bf[0] = Vsu[(8 * jd + g) * 36 + 8 * u + tq];
                bf[1] = Vsu[(8 * jd + g) * 36 + 8 * u + tq + 4];
                mma_f16(o[jd], af, bf);
            }
        }
        __syncthreads();
    }

    float ig = 1.0f / lg, i8 = 1.0f / l8;
    __half* y0 = y + (size_t)(b * S_ + r0) * RS + h * DK_;
    __half* y8 = y0 + 8 * RS;
    #pragma unroll
    for (int jd = 0; jd < 8; jd++) {
        *(__half2*)(y0 + 8 * jd + 2 * tq) =
            __floats2half2_rn(o[jd][0] * ig, o[jd][1] * ig);
        *(__half2*)(y8 + 8 * jd + 2 * tq) =
            __floats2half2_rn(o[jd][2] * i8, o[jd][3] * i8);
    }
}

// ---------------------------------------------------------------------------
// FP16 MMA GEMM: cp.async 4-stage pipeline + ldmatrix fragment loads.
// Smem rows are 80 bytes (40 halves): conflict-free for LDSM.
// ---------------------------------------------------------------------------
template <typename CT, bool GELU_ACT, bool QKV, int SPLITK, bool NGUARD>
__global__ void __launch_bounds__(256, 2)
mma_gemm(const __half* __restrict__ Ag, const __half* __restrict__ Bg,
         const float* __restrict__ biasg, CT* __restrict__ Cg,
         int M, int N, int K, int lda, int ldb, int ldc,
         const __half* Bg2, const float* bias2, CT* Cg2,
         const __half* Bg3, const float* bias3, CT* Cg3)
{
    constexpr int BM = 128, BK = 32, STAGES = 4;
    constexpr int STR = 20;                 // half2 units per row (80 B)
    constexpr int TSZ = BM * STR;           // per-stage units

    extern __shared__ unsigned smem_u[];
    unsigned* AsB = smem_u;
    unsigned* BsB = smem_u + STAGES * TSZ;

    const int tid  = threadIdx.x;
    const int wid  = tid >> 5;
    const int lane = tid & 31;
    const int g    = lane >> 2;
    const int tq   = lane & 3;
    const int m0   = NGUARD ? blockIdx.x * BM : blockIdx.y * BM;
    const int n0   = NGUARD ? blockIdx.y * BM : blockIdx.x * BM;
    const int z    = blockIdx.z;

    const __half* A = Ag;
    const __half* B = Bg;
    const float* bias = biasg;
    CT* C = Cg;

    if (QKV) {
        if (z == 1) { B = Bg2; bias = bias2; C = Cg2; }
        else if (z == 2) { B = Bg3; bias = bias3; C = Cg3; }
    } else if (SPLITK > 1) {
        C = Cg + (long long)z * M * ldc;
    }

    const int rowbase = (wid & 3) * 32;
    const int colbase = (wid >> 2) * 64;

    float acc[2][8][4];
    #pragma unroll
    for (int i = 0; i < 2; i++)
        #pragma unroll
        for (int j = 0; j < 8; j++)
            #pragma unroll
            for (int qq = 0; qq < 4; qq++) acc[i][j][qq] = 0.0f;

    int kbeg = 0, kend = K;
    if (SPLITK > 1) { kbeg = z * (K / SPLITK); kend = kbeg + K / SPLITK; }
    const int ntiles = (kend - kbeg) / BK;

    auto issue_stage = [&](int stage, int k0) {
        unsigned* as = AsB + stage * TSZ;
        unsigned* bs = BsB + stage * TSZ;
        #pragma unroll
        for (int i = 0; i < 2; i++) {
            int c = tid + i * 256;
            int row = c >> 2, ch = c & 3;
            cp16(&as[row * STR + ch * 4],
                 A + (long long)(m0 + row) * lda + k0 + ch * 8, true);
        }
        #pragma unroll
        for (int i = 0; i < 2; i++) {
            int c = tid + i * 256;
            int row = c >> 2, ch = c & 3;
            bool ok = !NGUARD || (n0 + row) < N;
            cp16(&bs[row * STR + ch * 4],
                 B + (long long)(n0 + row) * ldb + k0 + ch * 8, ok);
        }
        cp_commit();
    };

    // ldmatrix per-thread relative byte offsets
    const int lrow  = (lane & 7) + ((lane >> 3) & 1) * 8;
    const int lkoff = ((lane >> 4) & 1) * 16;
    const uint32_t offA = (uint32_t)((rowbase + lrow) * 80 + lkoff);
    const uint32_t offB = (uint32_t)((colbase + lrow) * 80 + lkoff);
    const uint32_t smemA = (uint32_t)__cvta_generic_to_shared(AsB);
    const uint32_t smemB = (uint32_t)__cvta_generic_to_shared(BsB);

    issue_stage(0, kbeg);
    if (ntiles > 1) issue_stage(1, kbeg + BK);
    if (ntiles > 2) issue_stage(2, kbeg + 2 * BK);

    for (int t = 0; t < ntiles; t++) {
        int rem = ntiles - 1 - t;
        if (rem >= 2)
            asm volatile("cp.async.wait_group 2;\n" ::: "memory");
        else if (rem == 1)
            asm volatile("cp.async.wait_group 1;\n" ::: "memory");
        else
            asm volatile("cp.async.wait_group 0;\n" ::: "memory");
        __syncthreads();

        if (t + 3 < ntiles) issue_stage((t + 3) % STAGES, kbeg + (t + 3) * BK);

        const uint32_t aBase = smemA + (uint32_t)((t % STAGES) * TSZ * 4) + offA;
        const uint32_t bBase = smemB + (uint32_t)((t % STAGES) * TSZ * 4) + offB;

        #pragma unroll
        for (int ks2 = 0; ks2 < 2; ks2++) {        // two k16 windows (+32 B)
            const uint32_t ko = ks2 * 32;
            unsigned af[2][4];
            ldsm4(af[0], aBase + ko);
            ldsm4(af[1], aBase + ko + 1280);       // +16 rows * 80 B
            unsigned bf[8][2];
            #pragma unroll
            for (int p = 0; p < 4; p++) {
                unsigned tmp[4];
                ldsm4(tmp, bBase + ko + p * 1280);
                bf[2 * p][0]     = tmp[0];
                bf[2 * p + 1][0] = tmp[1];
                bf[2 * p][1]     = tmp[2];
                bf[2 * p + 1][1] = tmp[3];
            }
            #pragma unroll
            for (int i = 0; i < 2; i++)
                #pragma unroll
                for (int j = 0; j < 8; j++)
                    mma_f16(acc[i][j], af[i], bf[j]);
        }
    }

    // ---- epilogue ----
    #pragma unroll
    for (int i = 0; i < 2; i++) {
        #pragma unroll
        for (int j = 0; j < 8; j++) {
            int r = m0 + rowbase + i * 16 + g;
            int c = n0 + colbase + j * 8 + tq * 2;
            #pragma unroll
            for (int hh = 0; hh < 2; hh++) {
                int rr = r + hh * 8;
                float v0 = acc[i][j][hh * 2 + 0];
                float v1 = acc[i][j][hh * 2 + 1];
                if constexpr (SPLITK > 1) {
                    *(float2*)((float*)C + (long long)rr * ldc + c) = make_float2(v0, v1);
                } else {
                    if (bias) { v0 += bias[c]; v1 += bias[c + 1]; }
                    if (GELU_ACT) { v0 = gelu_exact(v0); v1 = gelu_exact(v1); }
                    if constexpr (NGUARD) {
                        float* Cf = (float*)C;
                        if (c < N)     Cf[(long long)rr * ldc + c]     = v0;
                        if (c + 1 < N) Cf[(long long)rr * ldc + c + 1] = v1;
                    } else if constexpr (sizeof(CT) == 2) {
                        *(__half2*)((__half*)C + (long long)rr * ldc + c) =
                            __floats2half2_rn(v0, v1);
                    } else {
                        *(float2*)((float*)C + (long long)rr * ldc + c) =
                            make_float2(v0, v1);
                    }
                }
            }
        }
    }
}

// ---------------------------------------------------------------------------
// Split-K reduce (plain): x += partials + bias; fp16 shadow
// ---------------------------------------------------------------------------
__global__ void reduce_splitk(const float* __restrict__ part,
                              const float* __restrict__ bias,
                              float* __restrict__ x, __half* __restrict__ xr,
                              int NN, int ldc) {
    int idx = (blockIdx.x * 256 + threadIdx.x) * 4;
    float4 p0 = *(const float4*)(part + idx);
    float4 p1 = *(const float4*)(part + idx + NN);
    float4 xv = *(const float4*)(x + idx);
    float4 bv = *(const float4*)(bias + (idx % ldc));
    float4 o;
    o.x = xv.x + p0.x + p1.x + bv.x;
    o.y = xv.y + p0.y + p1.y + bv.y;
    o.z = xv.z + p0.z + p1.z + bv.z;
    o.w = xv.w + p0.w + p1.w + bv.w;
    *(float4*)(x + idx) = o;
    *(__half2*)(xr + idx)     = __floats2half2_rn(o.x, o.y);
    *(__half2*)(xr + idx + 2) = __floats2half2_rn(o.z, o.w);
}

// ---------------------------------------------------------------------------
// Fused split-K reduce + LayerNorm: x/xr update, then ln = LN(x) fp16
// grid NTOK, 256 threads (4 floats each)
// ---------------------------------------------------------------------------
__global__ void reduce_ln_kernel(const float* __restrict__ part,
                                 const float* __restrict__ bias,
                                 float* __restrict__ x, __half* __restrict__ xr,
                                 const float* __restrict__ g,
                                 const float* __restrict__ bb,
                                 __half* __restrict__ lnout, int NN) {
    const int row = blockIdx.x;
    const int tid = threadIdx.x;
    const int idx = row * D_ + tid * 4;
    __shared__ float rs[256];
    __shared__ float rq[256];

    float4 p0 = *(const float4*)(part + idx);
    float4 p1 = *(const float4*)(part + idx + NN);
    float4 xv = *(const float4*)(x + idx);
    float4 bv = *(const float4*)(bias + tid * 4);
    float4 o;
    o.x = xv.x + p0.x + p1.x + bv.x;
    o.y = xv.y + p0.y + p1.y + bv.y;
    o.z = xv.z + p0.z + p1.z + bv.z;
    o.w = xv.w + p0.w + p1.w + bv.w;
    *(float4*)(x + idx) = o;
    *(__half2*)(xr + idx)     = __floats2half2_rn(o.x, o.y);
    *(__half2*)(xr + idx + 2) = __floats2half2_rn(o.z, o.w);

    float s  = o.x + o.y + o.z + o.w;
    float sq = o.x * o.x + o.y * o.y + o.z * o.z + o.w * o.w;
    rs[tid] = s; rq[tid] = sq;
    __syncthreads();
    for (int off = 128; off > 0; off >>= 1) {
        if (tid < off) { rs[tid] += rs[tid + off]; rq[tid] += rq[tid + off]; }
        __syncthreads();
    }
    float mu  = rs[0] * (1.0f / D_);
    float var = rq[0] * (1.0f / D_) - mu * mu;
    float rstd = rsqrtf(var + 1e-5f);

    int c = tid * 4;
    float4 gv = *(const float4*)(g + c);
    float4 bv2 = *(const float4*)(bb + c);
    float o0 = (o.x - mu) * rstd * gv.x + bv2.x;
    float o1 = (o.y - mu) * rstd * gv.y + bv2.y;
    float o2 = (o.z - mu) * rstd * gv.z + bv2.z;
    float o3 = (o.w - mu) * rstd * gv.w + bv2.w;
    __half* op = lnout + (size_t)row * D_ + c;
    *(__half2*)(op)     = __floats2half2_rn(o0, o1);
    *(__half2*)(op + 2) = __floats2half2_rn(o2, o3);
}

// ---------------------------------------------------------------------------
// Host launcher
// ---------------------------------------------------------------------------
extern "C" void kernel_launch(void* const* d_in, const int* in_sizes, int n_in,
                              void* d_out, int out_size) {
    const int*   idx   = (const int*)  d_in[0];
    const float* te    = (const float*)d_in[1];
    const float* pe    = (const float*)d_in[2];
    const float* wq    = (const float*)d_in[3];
    const float* bq    = (const float*)d_in[4];
    const float* wk    = (const float*)d_in[5];
    const float* bk    = (const float*)d_in[6];
    const float* wv    = (const float*)d_in[7];
    const float* bv    = (const float*)d_in[8];
    const float* wo    = (const float*)d_in[9];
    const float* bo    = (const float*)d_in[10];
    const float* ln2g  = (const float*)d_in[11];
    const float* ln2b  = (const float*)d_in[12];
    const float* w1    = (const float*)d_in[13];
    const float* b1    = (const float*)d_in[14];
    const float* w2    = (const float*)d_in[15];
    const float* b2    = (const float*)d_in[16];
    const float* lnfg  = (const float*)d_in[17];
    const float* lnfb  = (const float*)d_in[18];
    float* out = (float*)d_out;

    float *x, *p;
    __half *xr, *q, *k, *v, *y, *ln, *h1;
    __half *wqT, *wkT, *wvT, *woT, *w1T, *w2T, *teh;
    cudaGetSymbolAddress((void**)&x,  g_x);
    cudaGetSymbolAddress((void**)&xr, g_xr);
    cudaGetSymbolAddress((void**)&q,  g_q);
    cudaGetSymbolAddress((void**)&k,  g_k);
    cudaGetSymbolAddress((void**)&v,  g_v);
    cudaGetSymbolAddress((void**)&y,  g_y);
    cudaGetSymbolAddress((void**)&ln, g_ln);
    cudaGetSymbolAddress((void**)&h1, g_h1);
    cudaGetSymbolAddress((void**)&p,  g_p);
    cudaGetSymbolAddress((void**)&wqT, g_wqT);
    cudaGetSymbolAddress((void**)&wkT, g_wkT);
    cudaGetSymbolAddress((void**)&wvT, g_wvT);
    cudaGetSymbolAddress((void**)&woT, g_woT);
    cudaGetSymbolAddress((void**)&w1T, g_w1T);
    cudaGetSymbolAddress((void**)&w2T, g_w2T);
    cudaGetSymbolAddress((void**)&teh, g_teh);

    // smem: 4 stages x (A 10240B + B 10240B) = 81920B
    const size_t smem_sz = 4 * 2 * 128 * 20 * 4;

    auto kq  = mma_gemm<__half, false, true,  1, false>;
    auto ksk = mma_gemm<float,  false, false, 2, false>;
    auto kw1 = mma_gemm<__half, true,  false, 1, false>;
    auto klg = mma_gemm<float,  false, false, 1, true>;
    cudaFuncSetAttribute(kq,  cudaFuncAttributeMaxDynamicSharedMemorySize, (int)smem_sz);
    cudaFuncSetAttribute(ksk, cudaFuncAttributeMaxDynamicSharedMemorySize, (int)smem_sz);
    cudaFuncSetAttribute(kw1, cudaFuncAttributeMaxDynamicSharedMemorySize, (int)smem_sz);
    cudaFuncSetAttribute(klg, cudaFuncAttributeMaxDynamicSharedMemorySize, (int)smem_sz);

    // ---- prepass ----
    dim3 tb(32, 8);
    transpose_cvt<<<dim3(32, 32, L_), tb>>>(wq, wqT, D_, D_);
    transpose_cvt<<<dim3(32, 32, L_), tb>>>(wk, wkT, D_, D_);
    transpose_cvt<<<dim3(32, 32, L_), tb>>>(wv, wvT, D_, D_);
    transpose_cvt<<<dim3(32, 32, L_), tb>>>(wo, woT, D_, D_);
    transpose_cvt<<<dim3(DFF_ / 32, D_ / 32, L_), tb>>>(w1, w1T, D_, DFF_);
    transpose_cvt<<<dim3(D_ / 32, DFF_ / 32, L_), tb>>>(w2, w2T, DFF_, D_);
    {
        long long nte = (long long)V_ * D_;
        int gte = (int)((nte + 2047) / 2048);
        cvt_f16_kernel<<<gte, 256>>>(te, teh, nte);
    }

    embed_kernel<<<NTOK, 256>>>(idx, te, pe, x, xr);

    const dim3 gQKV(D_ / 128, NTOK / 128, 3);
    const dim3 gSK (D_ / 128, NTOK / 128, 2);
    const dim3 gF  (DFF_ / 128, NTOK / 128);
    const dim3 gFA (S_ / 128, B_ * H_);
    const dim3 gLg (NTOK / 128, (V_ + 127) / 128);
    const int NN = NTOK * D_;

    for (int l = 0; l < L_; l++) {
        const __half* wq_l = wqT + (size_t)l * D_ * D_;
        const __half* wk_l = wkT + (size_t)l * D_ * D_;
        const __half* wv_l = wvT + (size_t)l * D_ * D_;
        const __half* wo_l = woT + (size_t)l * D_ * D_;
        const __half* w1_l = w1T + (size_t)l * D_ * DFF_;
        const __half* w2_l = w2T + (size_t)l * DFF_ * D_;

        kq<<<gQKV, 256, smem_sz>>>(
            xr, wq_l, bq + l * D_, q, NTOK, D_, D_, D_, D_, D_,
            wk_l, bk + l * D_, k, wv_l, bv + l * D_, v);

        flash_attn<<<gFA, 256>>>(q, k, v, y);

        // x += y @ wo^T + bo  --> fused with ln2 LayerNorm
        ksk<<<gSK, 256, smem_sz>>>(
            y, wo_l, nullptr, p, NTOK, D_, D_, D_, D_, D_,
            nullptr, nullptr, nullptr, nullptr, nullptr, nullptr);
        reduce_ln_kernel<<<NTOK, 256>>>(p, bo + l * D_, x, xr,
                                        ln2g + l * D_, ln2b + l * D_, ln, NN);

        kw1<<<gF, 256, smem_sz>>>(
            ln, w1_l, b1 + l * DFF_, h1, NTOK, DFF_, D_, D_, D_, DFF_,
            nullptr, nullptr, nullptr, nullptr, nullptr, nullptr);

        // x += h1 @ w2^T + b2
        ksk<<<gSK, 256, smem_sz>>>(
            h1, w2_l, nullptr, p, NTOK, D_, DFF_, DFF_, DFF_, D_,
            nullptr, nullptr, nullptr, nullptr, nullptr, nullptr);
        if (l < L_ - 1) {
            reduce_splitk<<<NN / 1024, 256>>>(p, b2 + l * D_, x, xr, NN, D_);
        } else {
            // fuse final reduce with lnf LayerNorm
            reduce_ln_kernel<<<NTOK, 256>>>(p, b2 + l * D_, x, xr,
                                            lnfg, lnfb, ln, NN);
        }
    }

    // logits = lnf(x) @ te^T
    klg<<<gLg, 256, smem_sz>>>(
        ln, teh, nullptr, out, NTOK, V_, D_, D_, D_, V_,
        nullptr, nullptr, nullptr, nullptr, nullptr, nullptr);
}